// round 1
// baseline (speedup 1.0000x reference)
#include <cuda_runtime.h>
#include <cstdint>

// Problem constants
#define N_PTS  524288
#define B_     2
#define D_     64
#define H_     256
#define W_     256
#define C_OUT  128
#define C_IN   64
#define MAPSZ  (B_*D_*H_*W_)   // 8,388,608

#define PT      128            // points per block
#define THREADS 256

// Dense coordinate -> point-id map (the rulebook source). 32MB static scratch.
__device__ int g_map[MAPSZ];

// ---------------------------------------------------------------------------
// Kernel 0: clear map to -1 (vectorized)
// ---------------------------------------------------------------------------
__global__ void k_clear() {
    int i = blockIdx.x * blockDim.x + threadIdx.x;
    reinterpret_cast<int4*>(g_map)[i] = make_int4(-1, -1, -1, -1);
}

// ---------------------------------------------------------------------------
// Kernel 1: scatter point ids into the map
// ---------------------------------------------------------------------------
__global__ void k_scatter(const int* __restrict__ coors) {
    int i = blockIdx.x * blockDim.x + threadIdx.x;
    if (i < N_PTS) {
        int4 c = *reinterpret_cast<const int4*>(coors + 4 * i);
        g_map[((c.x * D_ + c.y) * H_ + c.z) * W_ + c.w] = i;
    }
}

// ---------------------------------------------------------------------------
// Main fused kernel: sparse conv (gather form) + LSTM gates
// ---------------------------------------------------------------------------
struct Smem {
    float acc[PT][C_OUT];    // 64 KB output-stationary accumulators
    float W[C_IN][C_OUT];    // 32 KB current-offset weight tile
    float feat[32][C_IN];    // 8 KB gathered neighbor features (chunk of <=32)
    int   ep[PT];            // entry -> local point id
    int   en[PT];            // entry -> neighbor point id
    int   pz[PT], py[PT], px[PT], plin[PT];
    int   cnt;
};

__device__ __forceinline__ float sigm_f(float x) {
    return 1.0f / (1.0f + __expf(-x));
}
__device__ __forceinline__ float tanh_f(float x) {
    float e = __expf(2.0f * x);
    return 1.0f - 2.0f / (e + 1.0f);
}

__global__ __launch_bounds__(THREADS) void k_main(
    const float* __restrict__ xf, const float* __restrict__ hf,
    const float* __restrict__ cf, const float* __restrict__ weight,
    const float* __restrict__ bias, const int* __restrict__ coors,
    float* __restrict__ out)
{
    extern __shared__ char smem_raw[];
    Smem& s = *reinterpret_cast<Smem*>(smem_raw);
    const int tid   = threadIdx.x;
    const int wid   = tid >> 5;
    const int lane  = tid & 31;
    const int pbase = blockIdx.x * PT;

    // ---- point metadata ----
    if (tid < PT) {
        int gid = pbase + tid;
        int4 c = *reinterpret_cast<const int4*>(coors + 4 * gid);
        s.pz[tid]   = c.y;
        s.py[tid]   = c.z;
        s.px[tid]   = c.w;
        s.plin[tid] = ((c.x * D_ + c.y) * H_ + c.z) * W_ + c.w;
    }

    // ---- init accumulators with bias ----
    {
        float4* accv = reinterpret_cast<float4*>(&s.acc[0][0]);
        const float4* bv = reinterpret_cast<const float4*>(bias);
        #pragma unroll
        for (int i = tid; i < PT * C_OUT / 4; i += THREADS) {
            accv[i] = bv[i & 31];
        }
    }
    __syncthreads();

    // ---- 27 offsets ----
    for (int k = 0; k < 27; k++) {
        const int dz = k / 9 - 1;
        const int dy = (k / 3) % 3 - 1;
        const int dx = k % 3 - 1;

        if (tid == 0) s.cnt = 0;

        // stage W[k] into smem (weights stay hot in L2 across blocks)
        {
            const float4* wg = reinterpret_cast<const float4*>(weight + k * C_IN * C_OUT);
            float4* ws = reinterpret_cast<float4*>(&s.W[0][0]);
            #pragma unroll
            for (int i = 0; i < 8; i++) ws[tid + i * THREADS] = wg[tid + i * THREADS];
        }
        __syncthreads();   // cnt reset visible; prior-k compute finished (last chunk sync)

        // block-local rulebook: compact valid (point, neighbor) pairs
        if (tid < PT) {
            int nz = s.pz[tid] + dz, ny = s.py[tid] + dy, nx = s.px[tid] + dx;
            int nid = -1;
            if ((unsigned)nz < (unsigned)D_ && (unsigned)ny < (unsigned)H_ &&
                (unsigned)nx < (unsigned)W_) {
                nid = g_map[s.plin[tid] + dz * (H_ * W_) + dy * W_ + dx];
            }
            if (nid >= 0) {
                int pos = atomicAdd(&s.cnt, 1);
                s.ep[pos] = tid;
                s.en[pos] = nid;
            }
        }
        __syncthreads();
        const int cnt = s.cnt;

        for (int base = 0; base < cnt; base += 32) {
            const int m = min(cnt - base, 32);

            // gather neighbor feature rows into smem (8 threads per row)
            {
                int le = tid >> 3, sub = tid & 7;
                if (le < m) {
                    int nid = s.en[base + le];
                    float4 vx = reinterpret_cast<const float4*>(xf + (size_t)nid * 32)[sub];
                    float4 vh = reinterpret_cast<const float4*>(hf + (size_t)nid * 32)[sub];
                    *reinterpret_cast<float4*>(&s.feat[le][sub * 4])      = vx;
                    *reinterpret_cast<float4*>(&s.feat[le][32 + sub * 4]) = vh;
                }
            }
            __syncthreads();

            // tasks: (group of 4 entries) x (channel half). 8 warps round-robin.
            const int ntask = (((m + 3) >> 2) << 1);
            for (int t = wid; t < ntask; t += 8) {
                const int e0  = (t >> 1) * 4;
                const int col = (t & 1) * 64 + lane * 2;
                float2 r0 = {0.f, 0.f}, r1 = {0.f, 0.f};
                float2 r2 = {0.f, 0.f}, r3 = {0.f, 0.f};
                const float* wp = &s.W[0][col];
                #pragma unroll 16
                for (int j = 0; j < C_IN; j++) {
                    float2 w = *reinterpret_cast<const float2*>(wp + j * C_OUT);
                    float a = s.feat[e0    ][j];
                    float b = s.feat[e0 + 1][j];
                    float c = s.feat[e0 + 2][j];
                    float d = s.feat[e0 + 3][j];
                    r0.x = fmaf(a, w.x, r0.x); r0.y = fmaf(a, w.y, r0.y);
                    r1.x = fmaf(b, w.x, r1.x); r1.y = fmaf(b, w.y, r1.y);
                    r2.x = fmaf(c, w.x, r2.x); r2.y = fmaf(c, w.y, r2.y);
                    r3.x = fmaf(d, w.x, r3.x); r3.y = fmaf(d, w.y, r3.y);
                }
                // scatter into smem accumulators (unique point per entry within k)
                {
                    int p = s.ep[base + e0];
                    float2* a0 = reinterpret_cast<float2*>(&s.acc[p][col]);
                    float2 v = *a0; v.x += r0.x; v.y += r0.y; *a0 = v;
                }
                if (e0 + 1 < m) {
                    int p = s.ep[base + e0 + 1];
                    float2* a0 = reinterpret_cast<float2*>(&s.acc[p][col]);
                    float2 v = *a0; v.x += r1.x; v.y += r1.y; *a0 = v;
                }
                if (e0 + 2 < m) {
                    int p = s.ep[base + e0 + 2];
                    float2* a0 = reinterpret_cast<float2*>(&s.acc[p][col]);
                    float2 v = *a0; v.x += r2.x; v.y += r2.y; *a0 = v;
                }
                if (e0 + 3 < m) {
                    int p = s.ep[base + e0 + 3];
                    float2* a0 = reinterpret_cast<float2*>(&s.acc[p][col]);
                    float2 v = *a0; v.x += r3.x; v.y += r3.y; *a0 = v;
                }
            }
            __syncthreads();
        }
    }

    // ---- fused LSTM epilogue ----
    // out layout: h_next [N,32] then c_next [N,32]
    float* outh = out;
    float* outc = out + (size_t)N_PTS * 32;
    #pragma unroll
    for (int i = tid; i < PT * 32 / 4; i += THREADS) {   // 1024 float4 per block
        int p = i >> 3;
        int c = (i & 7) * 4;
        float4 gi = *reinterpret_cast<float4*>(&s.acc[p][c]);
        float4 gf = *reinterpret_cast<float4*>(&s.acc[p][32 + c]);
        float4 go = *reinterpret_cast<float4*>(&s.acc[p][64 + c]);
        float4 gg = *reinterpret_cast<float4*>(&s.acc[p][96 + c]);
        size_t ridx = (size_t)(pbase + p) * 8 + (c >> 2);
        float4 cp = reinterpret_cast<const float4*>(cf)[ridx];

        float4 cn, hn;
        {
            float ii = sigm_f(gi.x), ff = sigm_f(gf.x), oo = sigm_f(go.x), gt = tanh_f(gg.x);
            cn.x = ff * cp.x + ii * gt; hn.x = oo * tanh_f(cn.x);
        }
        {
            float ii = sigm_f(gi.y), ff = sigm_f(gf.y), oo = sigm_f(go.y), gt = tanh_f(gg.y);
            cn.y = ff * cp.y + ii * gt; hn.y = oo * tanh_f(cn.y);
        }
        {
            float ii = sigm_f(gi.z), ff = sigm_f(gf.z), oo = sigm_f(go.z), gt = tanh_f(gg.z);
            cn.z = ff * cp.z + ii * gt; hn.z = oo * tanh_f(cn.z);
        }
        {
            float ii = sigm_f(gi.w), ff = sigm_f(gf.w), oo = sigm_f(go.w), gt = tanh_f(gg.w);
            cn.w = ff * cp.w + ii * gt; hn.w = oo * tanh_f(cn.w);
        }
        reinterpret_cast<float4*>(outh)[ridx] = hn;
        reinterpret_cast<float4*>(outc)[ridx] = cn;
    }
}

// ---------------------------------------------------------------------------
// Launch
// ---------------------------------------------------------------------------
extern "C" void kernel_launch(void* const* d_in, const int* in_sizes, int n_in,
                              void* d_out, int out_size)
{
    const float* xf    = (const float*)d_in[0];
    const float* hf    = (const float*)d_in[1];
    const float* cf    = (const float*)d_in[2];
    const float* wt    = (const float*)d_in[3];
    const float* bs    = (const float*)d_in[4];
    const int*   coors = (const int*)  d_in[5];
    // d_in[6] (batch_size) unused — dims are compile-time constants.

    cudaFuncSetAttribute(k_main, cudaFuncAttributeMaxDynamicSharedMemorySize,
                         (int)sizeof(Smem));

    k_clear  <<<MAPSZ / 4 / 256, 256>>>();
    k_scatter<<<N_PTS / 256,    256>>>(coors);
    k_main   <<<N_PTS / PT, THREADS, sizeof(Smem)>>>(xf, hf, cf, wt, bs, coors,
                                                     (float*)d_out);
}

// round 3
// speedup vs baseline: 2.0226x; 2.0226x over previous
#include <cuda_runtime.h>
#include <cuda_fp16.h>
#include <cstdint>

// ---------------------------------------------------------------------------
// Problem constants
// ---------------------------------------------------------------------------
#define N_PTS   524288
#define Dd      64
#define Hh      256
#define Ww      256
#define MAPSZ   (2*Dd*Hh*Ww)     // 8,388,608
#define THREADS 512
#define PTS_BLK 256
#define NBLK    (N_PTS/PTS_BLK)  // 2048
#define CIN     64
#define COUT    128

#define A_PITCH 144              // 64 halfs (128B) + 16B pad -> conflict-free LDSM
#define B_PITCH 272              // 128 halfs (256B) + 16B pad

// smem byte offsets
#define OFF_BIAS  0              // 128 f32
#define OFF_FLAG  512            // 2 x 16 int
#define OFF_COORD 1024           // 256 x int4
#define OFF_A0    5120           // 256 x 144 = 36864
#define OFF_A1    41984
#define OFF_B0    78848          // 64 x 272 = 17408
#define OFF_B1    96256
#define SMEM_TOTAL 113664

__device__ int    g_map[MAPSZ];                    // 0 = empty, else pid+1
__device__ __half g_wh[27*CIN*COUT];               // permuted fp16 weights
__device__ __half g_feat[(size_t)N_PTS*CIN];       // fp16 [x||h] features

// ---------------------------------------------------------------------------
// helpers
// ---------------------------------------------------------------------------
__device__ __forceinline__ uint32_t smem_u32(const void* p) {
    uint32_t a;
    asm("{ .reg .u64 t; cvta.to.shared.u64 t, %1; cvt.u32.u64 %0, t; }"
        : "=r"(a) : "l"(p));
    return a;
}
__device__ __forceinline__ void ldsm4(uint32_t* r, uint32_t a) {
    asm volatile("ldmatrix.sync.aligned.m8n8.x4.shared.b16 {%0,%1,%2,%3},[%4];"
                 : "=r"(r[0]), "=r"(r[1]), "=r"(r[2]), "=r"(r[3]) : "r"(a));
}
__device__ __forceinline__ void ldsm4t(uint32_t* r, uint32_t a) {
    asm volatile("ldmatrix.sync.aligned.m8n8.x4.trans.shared.b16 {%0,%1,%2,%3},[%4];"
                 : "=r"(r[0]), "=r"(r[1]), "=r"(r[2]), "=r"(r[3]) : "r"(a));
}
__device__ __forceinline__ void mma16816(float* d, const uint32_t* a,
                                         const uint32_t* b) {
    asm volatile("mma.sync.aligned.m16n8k16.row.col.f32.f16.f16.f32 "
                 "{%0,%1,%2,%3},{%4,%5,%6,%7},{%8,%9},{%0,%1,%2,%3};"
                 : "+f"(d[0]), "+f"(d[1]), "+f"(d[2]), "+f"(d[3])
                 : "r"(a[0]), "r"(a[1]), "r"(a[2]), "r"(a[3]),
                   "r"(b[0]), "r"(b[1]));
}
__device__ __forceinline__ float sigm_f(float x) { return 1.0f/(1.0f+__expf(-x)); }
__device__ __forceinline__ float tanh_f(float x) {
    float e = __expf(2.0f*x); return 1.0f - 2.0f/(e + 1.0f);
}

// ---------------------------------------------------------------------------
// Pre-pass: fp16 feature staging, permuted fp16 weights, map scatter
// gate-column permutation: orig col n = gate*32+ch  ->  (ch>>4)*64 + gate*16 + (ch&15)
// ---------------------------------------------------------------------------
__global__ void k_pre(const float* __restrict__ xf, const float* __restrict__ hf,
                      const float* __restrict__ wt, const int* __restrict__ coors) {
    long long i = (long long)blockIdx.x * blockDim.x + threadIdx.x;
    if (i < (long long)N_PTS * CIN) {
        int pt = (int)(i >> 6), c = (int)(i & 63);
        float v = (c < 32) ? xf[pt*32 + c] : hf[pt*32 + (c - 32)];
        g_feat[i] = __float2half_rn(v);
    }
    if (i < 27*CIN*COUT) {
        int k   = (int)(i >> 13);
        int rem = (int)(i & 8191);
        int j = rem >> 7, n = rem & 127;
        int gate = n >> 5, ch = n & 31;
        int pos = (ch >> 4)*64 + gate*16 + (ch & 15);
        g_wh[k*8192 + j*128 + pos] = __float2half_rn(wt[i]);
    }
    if (i < N_PTS) {
        int4 c = reinterpret_cast<const int4*>(coors)[i];
        g_map[((c.x*Dd + c.y)*Hh + c.z)*Ww + c.w] = (int)i + 1;
    }
}

__global__ void k_unscatter(const int* __restrict__ coors) {
    int i = blockIdx.x * blockDim.x + threadIdx.x;
    if (i < N_PTS) {
        int4 c = reinterpret_cast<const int4*>(coors)[i];
        g_map[((c.x*Dd + c.y)*Hh + c.z)*Ww + c.w] = 0;
    }
}

// ---------------------------------------------------------------------------
// Main kernel
// ---------------------------------------------------------------------------
__global__ __launch_bounds__(THREADS, 1) void k_main(
    const float* __restrict__ cf, const float* __restrict__ bias,
    const int* __restrict__ coors, float* __restrict__ out)
{
    extern __shared__ __align__(16) char smem[];
    const uint32_t sb = smem_u32(smem);
    const int tid = threadIdx.x, w = tid >> 5, lane = tid & 31;
    const int gid = lane >> 2, tig = lane & 3;
    const int b = w >> 1, h = w & 1;          // band (m32), n-half
    const int pblk = blockIdx.x * PTS_BLK;

    float* s_bias  = reinterpret_cast<float*>(smem + OFF_BIAS);
    int*   s_flag  = reinterpret_cast<int*>(smem + OFF_FLAG);
    int4*  s_coord = reinterpret_cast<int4*>(smem + OFF_COORD);

    if (tid < 256) {
        int4 c = reinterpret_cast<const int4*>(coors)[pblk + tid];
        s_coord[tid] = make_int4(c.y, c.z, c.w,
                                 ((c.x*Dd + c.y)*Hh + c.z)*Ww + c.w);
    }
    if (tid < 128) {
        int gate = tid >> 5, ch = tid & 31;
        s_bias[(ch >> 4)*64 + gate*16 + (ch & 15)] = bias[tid];
    }
    __syncthreads();

    float acc[2][8][4];
    #pragma unroll
    for (int s = 0; s < 2; s++)
        #pragma unroll
        for (int t = 0; t < 8; t++)
            #pragma unroll
            for (int q = 0; q < 4; q++) acc[s][t][q] = 0.f;

    const int grow  = tid >> 1;      // gather row 0..255 (warp w -> rows 16w..16w+15)
    const int ghalf = tid & 1;
    const int4 pc = s_coord[grow];

    // ---- prologue: gather offset 0 + stage B0 ----
    {
        const int dz = -1, dy = -1, dx = -1;
        int nz = pc.x + dz, ny = pc.y + dy, nx = pc.z + dx;
        int nid = -1;
        if ((unsigned)nz < Dd && (unsigned)ny < Hh && (unsigned)nx < Ww)
            nid = g_map[pc.w + dz*65536 + dy*256 + dx] - 1;
        int4 gv[4] = {{0,0,0,0},{0,0,0,0},{0,0,0,0},{0,0,0,0}};
        if (nid >= 0) {
            const int4* fp = reinterpret_cast<const int4*>(g_feat) +
                             (size_t)nid*8 + ghalf*4;
            #pragma unroll
            for (int i = 0; i < 4; i++) gv[i] = fp[i];
        }
        unsigned bal = __ballot_sync(0xffffffffu, nid >= 0);
        if (lane == 0) s_flag[w] = (bal != 0);
        char* dstA = smem + OFF_A0 + grow*A_PITCH + ghalf*64;
        #pragma unroll
        for (int i = 0; i < 4; i++)
            *reinterpret_cast<int4*>(dstA + i*16) = gv[i];
        const int4* src = reinterpret_cast<const int4*>(g_wh) + tid*2;
        char* dstB = smem + OFF_B0 + (tid >> 3)*B_PITCH + (tid & 7)*32;
        *reinterpret_cast<int4*>(dstB)      = src[0];
        *reinterpret_cast<int4*>(dstB + 16) = src[1];
    }
    __syncthreads();

    // ---- 27 offsets ----
    for (int k = 0; k < 27; k++) {
        const int buf = k & 1;

        // prefetch offset k+1 (LDGs issued before compute for overlap)
        int4 gv[4] = {{0,0,0,0},{0,0,0,0},{0,0,0,0},{0,0,0,0}};
        int4 wv[2];
        int nid = -1;
        if (k < 26) {
            int kn = k + 1;
            int dz = kn/9 - 1, dy = (kn/3)%3 - 1, dx = kn%3 - 1;
            int nz = pc.x + dz, ny = pc.y + dy, nx = pc.z + dx;
            if ((unsigned)nz < Dd && (unsigned)ny < Hh && (unsigned)nx < Ww)
                nid = g_map[pc.w + dz*65536 + dy*256 + dx] - 1;
            if (nid >= 0) {
                const int4* fp = reinterpret_cast<const int4*>(g_feat) +
                                 (size_t)nid*8 + ghalf*4;
                #pragma unroll
                for (int i = 0; i < 4; i++) gv[i] = fp[i];
            }
            const int4* src = reinterpret_cast<const int4*>(g_wh) +
                              (size_t)kn*1024 + tid*2;
            wv[0] = src[0];
            wv[1] = src[1];
        }

        // compute offset k (skip if whole 32-row band has no valid neighbor)
        if (s_flag[buf*16 + 2*b] | s_flag[buf*16 + 2*b + 1]) {
            uint32_t abase = sb + (buf ? OFF_A1 : OFF_A0) +
                             (32*b + (lane & 15))*A_PITCH + (lane >> 4)*16;
            uint32_t bbase = sb + (buf ? OFF_B1 : OFF_B0) +
                             (lane & 15)*B_PITCH + h*128 + (lane >> 4)*16;
            #pragma unroll
            for (int kk = 0; kk < 4; kk++) {
                uint32_t a0[4], a1[4];
                ldsm4(a0, abase + kk*32);
                ldsm4(a1, abase + 16*A_PITCH + kk*32);
                #pragma unroll
                for (int np = 0; np < 4; np++) {
                    uint32_t bf[4];
                    ldsm4t(bf, bbase + kk*16*B_PITCH + np*32);
                    mma16816(acc[0][2*np],     a0, bf);
                    mma16816(acc[0][2*np + 1], a0, bf + 2);
                    mma16816(acc[1][2*np],     a1, bf);
                    mma16816(acc[1][2*np + 1], a1, bf + 2);
                }
            }
        }

        // store prefetched data into the other buffers
        if (k < 26) {
            const int nb = buf ^ 1;
            unsigned bal = __ballot_sync(0xffffffffu, nid >= 0);
            if (lane == 0) s_flag[nb*16 + w] = (bal != 0);
            char* dstA = smem + (nb ? OFF_A1 : OFF_A0) + grow*A_PITCH + ghalf*64;
            #pragma unroll
            for (int i = 0; i < 4; i++)
                *reinterpret_cast<int4*>(dstA + i*16) = gv[i];
            char* dstB = smem + (nb ? OFF_B1 : OFF_B0) +
                         (tid >> 3)*B_PITCH + (tid & 7)*32;
            *reinterpret_cast<int4*>(dstB)      = wv[0];
            *reinterpret_cast<int4*>(dstB + 16) = wv[1];
        }
        __syncthreads();
    }

    // ---- fused LSTM epilogue (fully thread-local thanks to gate permutation)
    float* outh = out;
    float* outc = out + (size_t)N_PTS * 32;
    #pragma unroll
    for (int sub = 0; sub < 2; sub++) {
        #pragma unroll
        for (int rh = 0; rh < 2; rh++) {
            const int row = pblk + 32*b + sub*16 + rh*8 + gid;
            #pragma unroll
            for (int p = 0; p < 2; p++) {
                const int ch  = h*16 + p*8 + 2*tig;
                const int bb  = h*64 + p*8 + 2*tig;
                float2 bi  = *reinterpret_cast<float2*>(&s_bias[bb]);
                float2 bff = *reinterpret_cast<float2*>(&s_bias[bb + 16]);
                float2 bo  = *reinterpret_cast<float2*>(&s_bias[bb + 32]);
                float2 bg  = *reinterpret_cast<float2*>(&s_bias[bb + 48]);
                float2 cp  = *reinterpret_cast<const float2*>(
                                 &cf[(size_t)row*32 + ch]);
                float hn[2], cn[2];
                #pragma unroll
                for (int q = 0; q < 2; q++) {
                    float iv = sigm_f(acc[sub][0 + p][rh*2 + q] + (q ? bi.y  : bi.x));
                    float fv = sigm_f(acc[sub][2 + p][rh*2 + q] + (q ? bff.y : bff.x));
                    float ov = sigm_f(acc[sub][4 + p][rh*2 + q] + (q ? bo.y  : bo.x));
                    float gt = tanh_f(acc[sub][6 + p][rh*2 + q] + (q ? bg.y  : bg.x));
                    float cpv = q ? cp.y : cp.x;
                    cn[q] = fv * cpv + iv * gt;
                    hn[q] = ov * tanh_f(cn[q]);
                }
                *reinterpret_cast<float2*>(&outh[(size_t)row*32 + ch]) =
                    make_float2(hn[0], hn[1]);
                *reinterpret_cast<float2*>(&outc[(size_t)row*32 + ch]) =
                    make_float2(cn[0], cn[1]);
            }
        }
    }
}

// ---------------------------------------------------------------------------
// Launch
// ---------------------------------------------------------------------------
extern "C" void kernel_launch(void* const* d_in, const int* in_sizes, int n_in,
                              void* d_out, int out_size)
{
    (void)in_sizes; (void)n_in; (void)out_size;
    const float* xf    = (const float*)d_in[0];
    const float* hf    = (const float*)d_in[1];
    const float* cf    = (const float*)d_in[2];
    const float* wt    = (const float*)d_in[3];
    const float* bs    = (const float*)d_in[4];
    const int*   coors = (const int*)  d_in[5];

    cudaFuncSetAttribute(k_main, cudaFuncAttributeMaxDynamicSharedMemorySize,
                         SMEM_TOTAL);

    k_pre      <<<65536, 512>>>(xf, hf, wt, coors);
    k_main     <<<NBLK, THREADS, SMEM_TOTAL>>>(cf, bs, coors, (float*)d_out);
    k_unscatter<<<1024, 512>>>(coors);
}

// round 8
// speedup vs baseline: 2.0925x; 1.0346x over previous
#include <cuda_runtime.h>
#include <cuda_fp16.h>
#include <cstdint>

// ---------------------------------------------------------------------------
// Problem constants
// ---------------------------------------------------------------------------
#define N_PTS   524288
#define Dd      64
#define Hh      256
#define Ww      256
#define MAPSZ   (2*Dd*Hh*Ww)     // 8,388,608
#define THREADS 512
#define PTS_BLK 512
#define NBLK    (N_PTS/PTS_BLK)  // 1024
#define CIN     64
#define COUT    128

#define A_PITCH 144              // 64 halfs (128B) + 16B pad
#define B_PITCH 272              // 128 halfs (256B) + 16B pad

// smem byte offsets
#define OFF_BIAS  0              // 128 f32
#define OFF_FLAG  512            // 2 bufs x 32 group flags (int)
#define OFF_COORD 1024           // 512 x int4
#define OFF_A0    9216           // 512*144 = 73728
#define OFF_A1    82944
#define OFF_B0    156672         // 64*272 = 17408
#define OFF_B1    174080
#define SMEM_TOTAL 191488

__device__ int    g_map[MAPSZ];                    // 0 = empty, else pid+1
__device__ __half g_wh[27*CIN*COUT];               // permuted fp16 weights
__device__ __half g_feat[(size_t)N_PTS*CIN];       // fp16 [x||h] features

// ---------------------------------------------------------------------------
// helpers
// ---------------------------------------------------------------------------
__device__ __forceinline__ uint32_t smem_u32(const void* p) {
    uint32_t a;
    asm("{ .reg .u64 t; cvta.to.shared.u64 t, %1; cvt.u32.u64 %0, t; }"
        : "=r"(a) : "l"(p));
    return a;
}
__device__ __forceinline__ uint32_t h2_bits(__half2 h) {
    return *reinterpret_cast<uint32_t*>(&h);
}
__device__ __forceinline__ void ldsm4(uint32_t* r, uint32_t a) {
    asm volatile("ldmatrix.sync.aligned.m8n8.x4.shared.b16 {%0,%1,%2,%3},[%4];"
                 : "=r"(r[0]), "=r"(r[1]), "=r"(r[2]), "=r"(r[3]) : "r"(a));
}
__device__ __forceinline__ void ldsm4t(uint32_t* r, uint32_t a) {
    asm volatile("ldmatrix.sync.aligned.m8n8.x4.trans.shared.b16 {%0,%1,%2,%3},[%4];"
                 : "=r"(r[0]), "=r"(r[1]), "=r"(r[2]), "=r"(r[3]) : "r"(a));
}
__device__ __forceinline__ void mma16816(float* d, const uint32_t* a,
                                         const uint32_t* b) {
    asm volatile("mma.sync.aligned.m16n8k16.row.col.f32.f16.f16.f32 "
                 "{%0,%1,%2,%3},{%4,%5,%6,%7},{%8,%9},{%0,%1,%2,%3};"
                 : "+f"(d[0]), "+f"(d[1]), "+f"(d[2]), "+f"(d[3])
                 : "r"(a[0]), "r"(a[1]), "r"(a[2]), "r"(a[3]),
                   "r"(b[0]), "r"(b[1]));
}
__device__ __forceinline__ void cpa16(uint32_t d, const void* s, int sz) {
    asm volatile("cp.async.cg.shared.global [%0], [%1], 16, %2;"
                 :: "r"(d), "l"(s), "r"(sz));
}
#define CPA_COMMIT() asm volatile("cp.async.commit_group;" ::: "memory")
#define CPA_WAIT1()  asm volatile("cp.async.wait_group 1;"  ::: "memory")

__device__ __forceinline__ float sigm_f(float x) { return 1.0f/(1.0f+__expf(-x)); }
__device__ __forceinline__ float tanh_f(float x) {
    float e = __expf(2.0f*x); return 1.0f - 2.0f/(e + 1.0f);
}

// ---------------------------------------------------------------------------
// Pre-pass: fp16 feature staging (8 halfs/thread), permuted fp16 weights,
// map scatter.  gate permutation: n = gate*32+ch -> (ch>>4)*64 + gate*16 + (ch&15)
// ---------------------------------------------------------------------------
__global__ __launch_bounds__(512) void k_pre(
    const float* __restrict__ xf, const float* __restrict__ hf,
    const float* __restrict__ wt, const int* __restrict__ coors)
{
    int i = blockIdx.x * blockDim.x + threadIdx.x;   // 8192*512 = 4,194,304
    {
        int pt = i >> 3, seg = i & 7;
        const float* bp = (seg < 4) ? xf + (size_t)pt*32 + seg*8
                                    : hf + (size_t)pt*32 + (seg - 4)*8;
        float4 v0 = reinterpret_cast<const float4*>(bp)[0];
        float4 v1 = reinterpret_cast<const float4*>(bp)[1];
        uint4 pk;
        pk.x = h2_bits(__floats2half2_rn(v0.x, v0.y));
        pk.y = h2_bits(__floats2half2_rn(v0.z, v0.w));
        pk.z = h2_bits(__floats2half2_rn(v1.x, v1.y));
        pk.w = h2_bits(__floats2half2_rn(v1.z, v1.w));
        reinterpret_cast<uint4*>(g_feat)[i] = pk;
    }
    if (i < 27*CIN*COUT) {
        int k   = i >> 13;
        int rem = i & 8191;
        int j = rem >> 7, n = rem & 127;
        int gate = n >> 5, ch = n & 31;
        int pos = (ch >> 4)*64 + gate*16 + (ch & 15);
        g_wh[k*8192 + j*128 + pos] = __float2half_rn(wt[i]);
    }
    if (i < N_PTS) {
        int4 c = reinterpret_cast<const int4*>(coors)[i];
        g_map[((c.x*Dd + c.y)*Hh + c.z)*Ww + c.w] = i + 1;
    }
}

__global__ void k_unscatter(const int* __restrict__ coors) {
    int i = blockIdx.x * blockDim.x + threadIdx.x;
    if (i < N_PTS) {
        int4 c = reinterpret_cast<const int4*>(coors)[i];
        g_map[((c.x*Dd + c.y)*Hh + c.z)*Ww + c.w] = 0;
    }
}

// ---------------------------------------------------------------------------
// Main kernel: 512 pts/block, 16 warps = 8 m64-bands x 2 n64-halves.
// m16-granular skip; cp.async zfill gather pipeline; register accumulation
// across all 27 offsets; fused LSTM epilogue.
// ---------------------------------------------------------------------------
__global__ __launch_bounds__(THREADS, 1) void k_main(
    const float* __restrict__ cf, const float* __restrict__ bias,
    const int* __restrict__ coors, float* __restrict__ out)
{
    extern __shared__ __align__(16) char smem[];
    const uint32_t sb = smem_u32(smem);
    const int tid = threadIdx.x, wid = tid >> 5, lane = tid & 31;
    const int gid = lane >> 2, tig = lane & 3;
    const int wm = wid >> 1, h = wid & 1;     // m64 band, n64 half
    const int pblk = blockIdx.x * PTS_BLK;

    float* s_bias  = reinterpret_cast<float*>(smem + OFF_BIAS);
    int*   s_flag  = reinterpret_cast<int*>(smem + OFF_FLAG);
    int4*  s_coord = reinterpret_cast<int4*>(smem + OFF_COORD);

    {
        int4 c = reinterpret_cast<const int4*>(coors)[pblk + tid];
        s_coord[tid] = make_int4(c.y, c.z, c.w,
                                 ((c.x*Dd + c.y)*Hh + c.z)*Ww + c.w);
    }
    if (tid < 128) {
        int gate = tid >> 5, ch = tid & 31;
        s_bias[(ch >> 4)*64 + gate*16 + (ch & 15)] = bias[tid];
    }
    __syncthreads();

    const int4 pc = s_coord[tid];             // this thread gathers row `tid`

    float acc[4][8][4];
    #pragma unroll
    for (int s = 0; s < 4; s++)
        #pragma unroll
        for (int t = 0; t < 8; t++)
            #pragma unroll
            for (int q = 0; q < 4; q++) acc[s][t][q] = 0.f;

    // ---- gather-issue for offset kn into buffer nb (cp.async) ----
    auto issue = [&](int kn, int nb) {
        const int dz = kn/9 - 1, dy = (kn/3)%3 - 1, dx = kn%3 - 1;
        int nz = pc.x + dz, ny = pc.y + dy, nx = pc.z + dx;
        int nid = -1;
        if ((unsigned)nz < Dd && (unsigned)ny < Hh && (unsigned)nx < Ww)
            nid = g_map[pc.w + dz*65536 + dy*256 + dx] - 1;
        unsigned bal = __ballot_sync(0xffffffffu, nid >= 0);
        if (lane == 0) {
            s_flag[nb*32 + 2*wid]     = (bal & 0xFFFFu) != 0;
            s_flag[nb*32 + 2*wid + 1] = (bal >> 16)     != 0;
        }
        unsigned gm = (lane < 16) ? (bal & 0xFFFFu) : (bal >> 16);
        if (gm) {   // group has >=1 valid row: load (or zero-fill) my row
            const char* src = reinterpret_cast<const char*>(
                g_feat + (size_t)max(nid, 0)*64);
            const int sz = (nid >= 0) ? 16 : 0;
            uint32_t dst = sb + (nb ? OFF_A1 : OFF_A0) + tid*A_PITCH;
            #pragma unroll
            for (int c = 0; c < 8; c++) cpa16(dst + c*16, src + c*16, sz);
        }
        // B = W[kn] (32B per thread)
        const char* wsrc = reinterpret_cast<const char*>(g_wh) +
                           (size_t)kn*16384 + tid*32;
        uint32_t wdst = sb + (nb ? OFF_B1 : OFF_B0) +
                        (tid >> 3)*B_PITCH + (tid & 7)*32;
        cpa16(wdst,      wsrc,      16);
        cpa16(wdst + 16, wsrc + 16, 16);
    };

    // prologue
    issue(0, 0);
    CPA_COMMIT();

    for (int k = 0; k < 27; k++) {
        const int buf = k & 1;
        if (k < 26) issue(k + 1, (k + 1) & 1);
        CPA_COMMIT();
        CPA_WAIT1();
        __syncthreads();

        int fs[4];
        #pragma unroll
        for (int s = 0; s < 4; s++) fs[s] = s_flag[buf*32 + 4*wm + s];

        if (fs[0] | fs[1] | fs[2] | fs[3]) {
            uint32_t abase = sb + (buf ? OFF_A1 : OFF_A0) +
                             (64*wm + (lane & 15))*A_PITCH + (lane >> 4)*16;
            uint32_t bbase = sb + (buf ? OFF_B1 : OFF_B0) +
                             (lane & 15)*B_PITCH + h*128 + (lane >> 4)*16;
            #pragma unroll
            for (int kk = 0; kk < 4; kk++) {
                uint32_t bf[4][4];
                #pragma unroll
                for (int np = 0; np < 4; np++)
                    ldsm4t(bf[np], bbase + kk*16*B_PITCH + np*32);
                #pragma unroll
                for (int s = 0; s < 4; s++) {
                    if (fs[s]) {
                        uint32_t a[4];
                        ldsm4(a, abase + s*16*A_PITCH + kk*32);
                        #pragma unroll
                        for (int np = 0; np < 4; np++) {
                            mma16816(acc[s][2*np],     a, bf[np]);
                            mma16816(acc[s][2*np + 1], a, bf[np] + 2);
                        }
                    }
                }
            }
        }
        __syncthreads();
    }

    // ---- fused LSTM epilogue (thread-local via gate permutation) ----
    float* outh = out;
    float* outc = out + (size_t)N_PTS * 32;
    #pragma unroll
    for (int s = 0; s < 4; s++) {
        #pragma unroll
        for (int rh = 0; rh < 2; rh++) {
            const int row = pblk + 64*wm + 16*s + rh*8 + gid;
            #pragma unroll
            for (int p = 0; p < 2; p++) {
                const int ch = h*16 + p*8 + 2*tig;
                const int bb = h*64 + p*8 + 2*tig;
                float2 bi  = *reinterpret_cast<float2*>(&s_bias[bb]);
                float2 bff = *reinterpret_cast<float2*>(&s_bias[bb + 16]);
                float2 bo  = *reinterpret_cast<float2*>(&s_bias[bb + 32]);
                float2 bg  = *reinterpret_cast<float2*>(&s_bias[bb + 48]);
                float2 cp  = *reinterpret_cast<const float2*>(
                                 &cf[(size_t)row*32 + ch]);
                float hn[2], cn[2];
                #pragma unroll
                for (int q = 0; q < 2; q++) {
                    float iv = sigm_f(acc[s][0 + p][rh*2 + q] + (q ? bi.y  : bi.x));
                    float fv = sigm_f(acc[s][2 + p][rh*2 + q] + (q ? bff.y : bff.x));
                    float ov = sigm_f(acc[s][4 + p][rh*2 + q] + (q ? bo.y  : bo.x));
                    float gt = tanh_f(acc[s][6 + p][rh*2 + q] + (q ? bg.y  : bg.x));
                    float cpv = q ? cp.y : cp.x;
                    cn[q] = fv * cpv + iv * gt;
                    hn[q] = ov * tanh_f(cn[q]);
                }
                *reinterpret_cast<float2*>(&outh[(size_t)row*32 + ch]) =
                    make_float2(hn[0], hn[1]);
                *reinterpret_cast<float2*>(&outc[(size_t)row*32 + ch]) =
                    make_float2(cn[0], cn[1]);
            }
        }
    }
}

// ---------------------------------------------------------------------------
// Launch
// ---------------------------------------------------------------------------
extern "C" void kernel_launch(void* const* d_in, const int* in_sizes, int n_in,
                              void* d_out, int out_size)
{
    (void)in_sizes; (void)n_in; (void)out_size;
    const float* xf    = (const float*)d_in[0];
    const float* hf    = (const float*)d_in[1];
    const float* cf    = (const float*)d_in[2];
    const float* wt    = (const float*)d_in[3];
    const float* bs    = (const float*)d_in[4];
    const int*   coors = (const int*)  d_in[5];

    cudaFuncSetAttribute(k_main, cudaFuncAttributeMaxDynamicSharedMemorySize,
                         SMEM_TOTAL);

    k_pre      <<<8192, 512>>>(xf, hf, wt, coors);
    k_main     <<<NBLK, THREADS, SMEM_TOTAL>>>(cf, bs, coors, (float*)d_out);
    k_unscatter<<<1024, 512>>>(coors);
}